// round 6
// baseline (speedup 1.0000x reference)
#include <cuda_runtime.h>
#include <math.h>
#include <stdint.h>

// ---------------------------------------------------------------------------
// QuickPatternMatchingLoss
//   out[b] = log( (1/ls) * sum_{l: mask} sum_o ss_hmm[o,l] *
//                 softmax_o( W[:, :20] . x[b,1:,l] + slog[:,l] ) )
//   slog[o,l] = b[o] + sum_h W[o,20+h] * seq_hmm[h,l]   (tiny prologue kernel)
//   mask[b,l] = ( max_{c>=1} x[b,c,l] > x[b,0,l] )
//
// R6: one CTA per row; the 43008-byte contiguous row is fetched with ONE
// cp.async.bulk (TMA) into static smem + mbarrier expect_tx. This removes the
// register-limited LDG front-batching bottleneck identified in R0/R5 (DRAM%
// tracked regs-for-loads, not occupancy). 5 CTAs/SM by smem; waiting CTAs'
// TMA fills overlap running CTAs' compute. Tables stay __ldg (L2-hot),
// issued before the mbarrier wait.
// ---------------------------------------------------------------------------

#define MAX_L 2048
__device__ float g_slog[3 * MAX_L];   // batch-invariant logits

// fixed fast-path shape
#define FL 512          // L
#define FC 21           // channels
#define ROW_BYTES (FC * FL * 4)   // 43008

__device__ __forceinline__ uint32_t smem_u32(const void* p) {
    uint32_t a;
    asm("{ .reg .u64 t; cvta.to.shared.u64 t, %1; cvt.u32.u64 %0, t; }"
        : "=r"(a) : "l"(p));
    return a;
}

__device__ __forceinline__ void mbar_init(uint32_t mbar, uint32_t count) {
    asm volatile("mbarrier.init.shared.b64 [%0], %1;" :: "r"(mbar), "r"(count) : "memory");
}
__device__ __forceinline__ void mbar_expect_tx(uint32_t mbar, uint32_t bytes) {
    asm volatile("mbarrier.arrive.expect_tx.shared.b64 _, [%0], %1;"
                 :: "r"(mbar), "r"(bytes) : "memory");
}
__device__ __forceinline__ void bulk_g2s(uint32_t dst, const void* src,
                                         uint32_t bytes, uint32_t mbar) {
    asm volatile(
        "cp.async.bulk.shared::cta.global.mbarrier::complete_tx::bytes "
        "[%0], [%1], %2, [%3];"
        :: "r"(dst), "l"(src), "r"(bytes), "r"(mbar) : "memory");
}
__device__ __forceinline__ void mbar_wait(uint32_t mbar, uint32_t parity) {
    uint32_t done;
    asm volatile(
        "{\n\t.reg .pred p;\n\t"
        "mbarrier.try_wait.parity.acquire.cta.shared::cta.b64 p, [%1], %2;\n\t"
        "selp.b32 %0, 1, 0, p;\n\t}"
        : "=r"(done) : "r"(mbar), "r"(parity) : "memory");
    if (!done) {
        asm volatile(
            "{\n\t.reg .pred P1;\n\t"
            "WAIT_LOOP_%=:\n\t"
            "mbarrier.try_wait.parity.acquire.cta.shared::cta.b64 P1, [%0], %1, 0x989680;\n\t"
            "@P1 bra.uni WAIT_DONE_%=;\n\t"
            "bra.uni WAIT_LOOP_%=;\n\t"
            "WAIT_DONE_%=:\n\t}"
            :: "r"(mbar), "r"(parity) : "memory");
    }
}

// ---- prologue: slog[o,l] = b[o] + sum_h W[o,20+h] * seq_hmm[h,l] ----------
__global__ void slog_kernel(const float* __restrict__ seq_hmm,
                            const float* __restrict__ W,
                            const float* __restrict__ bvec,
                            int L, int H, int wstride)
{
    int l = blockIdx.x * blockDim.x + threadIdx.x;
    if (l >= L) return;
    float s0 = bvec[0], s1 = bvec[1], s2 = bvec[2];
    for (int h = 0; h < H; ++h) {
        float v = __ldg(&seq_hmm[h * L + l]);
        s0 = fmaf(__ldg(&W[0 * wstride + 20 + h]), v, s0);
        s1 = fmaf(__ldg(&W[1 * wstride + 20 + h]), v, s1);
        s2 = fmaf(__ldg(&W[2 * wstride + 20 + h]), v, s2);
    }
    g_slog[0 * L + l] = s0;
    g_slog[1 * L + l] = s1;
    g_slog[2 * L + l] = s2;
}

// ---- fast-path main kernel: TMA bulk row fetch + smem compute ---------------
__global__ void __launch_bounds__(128, 5)
qpml_tma(const float* __restrict__ x,
         const float* __restrict__ ss_hmm,
         const float* __restrict__ W,
         float* __restrict__ out,
         int wstride)
{
    const int b = blockIdx.x;
    const int t = threadIdx.x;

    __shared__ __align__(16) float x_s[FC * FL];   // 43008 B
    __shared__ float sW0[20], sW1[20], sW2[20];
    __shared__ __align__(8) unsigned long long mbar_storage;
    __shared__ float rs[2][4];

    const uint32_t mbar = smem_u32(&mbar_storage);

    if (t == 0) mbar_init(mbar, 1);
    if (t < 20) {
        sW0[t] = __ldg(&W[0 * wstride + t]);
        sW1[t] = __ldg(&W[1 * wstride + t]);
        sW2[t] = __ldg(&W[2 * wstride + t]);
    }
    __syncthreads();

    if (t == 0) {
        mbar_expect_tx(mbar, ROW_BYTES);
        const char* src = (const char*)x + (size_t)b * ROW_BYTES;
        bulk_g2s(smem_u32(x_s), src, ROW_BYTES, mbar);
    }

    // L2-hot table loads in flight while TMA fills smem.
    const int i = t;                      // float4 column-group, 128 of them
    float4 sl0 = __ldg((const float4*)&g_slog[0 * FL] + i);
    float4 sl1 = __ldg((const float4*)&g_slog[1 * FL] + i);
    float4 sl2 = __ldg((const float4*)&g_slog[2 * FL] + i);
    float4 h0  = __ldg((const float4*)&ss_hmm[0 * FL] + i);
    float4 h1  = __ldg((const float4*)&ss_hmm[1 * FL] + i);
    float4 h2  = __ldg((const float4*)&ss_hmm[2 * FL] + i);

    mbar_wait(mbar, 0);

    // gap channel
    float4 v0 = ((const float4*)x_s)[i];
    float x0[4] = {v0.x, v0.y, v0.z, v0.w};
    float mx[4] = {-INFINITY, -INFINITY, -INFINITY, -INFINITY};
    float a0[4] = {0.f, 0.f, 0.f, 0.f};
    float a1[4] = {0.f, 0.f, 0.f, 0.f};
    float a2[4] = {0.f, 0.f, 0.f, 0.f};

    #pragma unroll
    for (int c = 1; c < FC; ++c) {
        float4 v = ((const float4*)x_s)[c * (FL / 4) + i];
        float vv[4] = {v.x, v.y, v.z, v.w};
        float w0 = sW0[c - 1], w1 = sW1[c - 1], w2 = sW2[c - 1];
        #pragma unroll
        for (int j = 0; j < 4; ++j) {
            mx[j] = fmaxf(mx[j], vv[j]);
            a0[j] = fmaf(w0, vv[j], a0[j]);
            a1[j] = fmaf(w1, vv[j], a1[j]);
            a2[j] = fmaf(w2, vv[j], a2[j]);
        }
    }

    float sla0[4] = {sl0.x, sl0.y, sl0.z, sl0.w};
    float sla1[4] = {sl1.x, sl1.y, sl1.z, sl1.w};
    float sla2[4] = {sl2.x, sl2.y, sl2.z, sl2.w};
    float ha0[4]  = {h0.x, h0.y, h0.z, h0.w};
    float ha1[4]  = {h1.x, h1.y, h1.z, h1.w};
    float ha2[4]  = {h2.x, h2.y, h2.z, h2.w};

    float contrib = 0.f, cnt = 0.f;
    #pragma unroll
    for (int j = 0; j < 4; ++j) {
        float e0 = __expf(a0[j] + sla0[j]);
        float e1 = __expf(a1[j] + sla1[j]);
        float e2 = __expf(a2[j] + sla2[j]);
        float num = ha0[j] * e0 + ha1[j] * e1 + ha2[j] * e2;
        float den = e0 + e1 + e2;
        bool m = mx[j] > x0[j];
        contrib += m ? __fdividef(num, den) : 0.f;
        cnt     += m ? 1.f : 0.f;
    }

    #pragma unroll
    for (int off = 16; off > 0; off >>= 1) {
        contrib += __shfl_down_sync(0xffffffffu, contrib, off);
        cnt     += __shfl_down_sync(0xffffffffu, cnt, off);
    }
    if ((t & 31) == 0) { rs[0][t >> 5] = contrib; rs[1][t >> 5] = cnt; }
    __syncthreads();
    if (t == 0) {
        float s = rs[0][0] + rs[0][1] + rs[0][2] + rs[0][3];
        float c = rs[1][0] + rs[1][1] + rs[1][2] + rs[1][3];
        out[b] = logf(s / c);
    }
}

// ---- general fallback (R5 path) ---------------------------------------------
template <int NC>
__global__ void __launch_bounds__(128, 6)
qpml_kernel(const float* __restrict__ x,
            const float* __restrict__ ss_hmm,
            const float* __restrict__ W,
            float* __restrict__ out,
            int L, int nc_rt, int wstride)
{
    const int b = blockIdx.x;
    const int t = threadIdx.x;
    const int C = (NC > 0) ? NC : nc_rt;
    const int Lv = L >> 2;

    __shared__ float sW0[20], sW1[20], sW2[20];
    if (t < 20) {
        sW0[t] = __ldg(&W[0 * wstride + t]);
        sW1[t] = __ldg(&W[1 * wstride + t]);
        sW2[t] = __ldg(&W[2 * wstride + t]);
    }
    __syncthreads();

    const float4* xb = (const float4*)(x + (size_t)b * (size_t)C * (size_t)L);
    float contrib = 0.f, cnt = 0.f;

    for (int i = t; i < Lv; i += 128) {
        float4 sl0 = __ldg((const float4*)&g_slog[0 * L] + i);
        float4 sl1 = __ldg((const float4*)&g_slog[1 * L] + i);
        float4 sl2 = __ldg((const float4*)&g_slog[2 * L] + i);
        float4 h0  = __ldg((const float4*)&ss_hmm[0 * L] + i);
        float4 h1  = __ldg((const float4*)&ss_hmm[1 * L] + i);
        float4 h2  = __ldg((const float4*)&ss_hmm[2 * L] + i);

        float4 v0 = __ldcs(&xb[i]);
        float x0[4] = {v0.x, v0.y, v0.z, v0.w};
        float mx[4] = {-INFINITY, -INFINITY, -INFINITY, -INFINITY};
        float a0[4] = {0.f, 0.f, 0.f, 0.f};
        float a1[4] = {0.f, 0.f, 0.f, 0.f};
        float a2[4] = {0.f, 0.f, 0.f, 0.f};

        for (int c = 1; c < C; ++c) {
            float4 v = __ldcs(&xb[c * Lv + i]);
            float vv[4] = {v.x, v.y, v.z, v.w};
            float w0 = sW0[c - 1], w1 = sW1[c - 1], w2 = sW2[c - 1];
            #pragma unroll
            for (int j = 0; j < 4; ++j) {
                mx[j] = fmaxf(mx[j], vv[j]);
                a0[j] = fmaf(w0, vv[j], a0[j]);
                a1[j] = fmaf(w1, vv[j], a1[j]);
                a2[j] = fmaf(w2, vv[j], a2[j]);
            }
        }

        float sla0[4] = {sl0.x, sl0.y, sl0.z, sl0.w};
        float sla1[4] = {sl1.x, sl1.y, sl1.z, sl1.w};
        float sla2[4] = {sl2.x, sl2.y, sl2.z, sl2.w};
        float ha0[4]  = {h0.x, h0.y, h0.z, h0.w};
        float ha1[4]  = {h1.x, h1.y, h1.z, h1.w};
        float ha2[4]  = {h2.x, h2.y, h2.z, h2.w};

        #pragma unroll
        for (int j = 0; j < 4; ++j) {
            float e0 = __expf(a0[j] + sla0[j]);
            float e1 = __expf(a1[j] + sla1[j]);
            float e2 = __expf(a2[j] + sla2[j]);
            float num = ha0[j] * e0 + ha1[j] * e1 + ha2[j] * e2;
            float den = e0 + e1 + e2;
            bool m = mx[j] > x0[j];
            contrib += m ? __fdividef(num, den) : 0.f;
            cnt     += m ? 1.f : 0.f;
        }
    }

    #pragma unroll
    for (int off = 16; off > 0; off >>= 1) {
        contrib += __shfl_down_sync(0xffffffffu, contrib, off);
        cnt     += __shfl_down_sync(0xffffffffu, cnt, off);
    }
    __shared__ float rs[2][4];
    if ((t & 31) == 0) { rs[0][t >> 5] = contrib; rs[1][t >> 5] = cnt; }
    __syncthreads();
    if (t == 0) {
        float s = rs[0][0] + rs[0][1] + rs[0][2] + rs[0][3];
        float c = rs[1][0] + rs[1][1] + rs[1][2] + rs[1][3];
        out[b] = logf(s / c);
    }
}

__global__ void qpml_kernel_scalar(const float* __restrict__ x,
                                   const float* __restrict__ ss_hmm,
                                   const float* __restrict__ W,
                                   float* __restrict__ out,
                                   int L, int C, int wstride)
{
    const int b = blockIdx.x;
    const int t = threadIdx.x;
    const float* xb = x + (size_t)b * (size_t)C * (size_t)L;

    float contrib = 0.f, cnt = 0.f;
    for (int l = t; l < L; l += blockDim.x) {
        float x0 = xb[l];
        float mx = -INFINITY;
        float a0 = 0.f, a1 = 0.f, a2 = 0.f;
        for (int c = 1; c < C; ++c) {
            float v = xb[c * L + l];
            mx = fmaxf(mx, v);
            a0 = fmaf(W[0 * wstride + c - 1], v, a0);
            a1 = fmaf(W[1 * wstride + c - 1], v, a1);
            a2 = fmaf(W[2 * wstride + c - 1], v, a2);
        }
        float e0 = __expf(a0 + g_slog[0 * L + l]);
        float e1 = __expf(a1 + g_slog[1 * L + l]);
        float e2 = __expf(a2 + g_slog[2 * L + l]);
        float num = ss_hmm[0 * L + l] * e0 + ss_hmm[1 * L + l] * e1
                  + ss_hmm[2 * L + l] * e2;
        if (mx > x0) { contrib += num / (e0 + e1 + e2); cnt += 1.f; }
    }
    #pragma unroll
    for (int off = 16; off > 0; off >>= 1) {
        contrib += __shfl_down_sync(0xffffffffu, contrib, off);
        cnt     += __shfl_down_sync(0xffffffffu, cnt, off);
    }
    __shared__ float rs[2][32];
    int nw = (blockDim.x + 31) >> 5;
    if ((t & 31) == 0) { rs[0][t >> 5] = contrib; rs[1][t >> 5] = cnt; }
    __syncthreads();
    if (t == 0) {
        float s = 0.f, c = 0.f;
        for (int w = 0; w < nw; ++w) { s += rs[0][w]; c += rs[1][w]; }
        out[b] = logf(s / c);
    }
}

extern "C" void kernel_launch(void* const* d_in, const int* in_sizes, int n_in,
                              void* d_out, int out_size)
{
    const float* x       = (const float*)d_in[0];   // [B, 21, L]
    const float* seq_hmm = (const float*)d_in[1];   // [H, L]
    const float* ss_hmm  = (const float*)d_in[2];   // [3, L]
    const float* W       = (const float*)d_in[3];   // [3, 20+H]
    const float* bvec    = (const float*)d_in[4];   // [3]
    float* out = (float*)d_out;

    const int B       = out_size;                   // 4096
    const int L       = in_sizes[2] / 3;            // 512
    const int H       = in_sizes[1] / L;            // 30
    const int C       = in_sizes[0] / (B * L);      // 21
    const int wstride = in_sizes[3] / 3;            // 20 + H = 50

    slog_kernel<<<(L + 255) / 256, 256>>>(seq_hmm, W, bvec, L, H, wstride);

    if (C == FC && L == FL) {
        qpml_tma<<<B, 128>>>(x, ss_hmm, W, out, wstride);
    } else if ((L & 3) == 0 && L <= MAX_L) {
        qpml_kernel<0><<<B, 128>>>(x, ss_hmm, W, out, L, C, wstride);
    } else {
        qpml_kernel_scalar<<<B, 128>>>(x, ss_hmm, W, out, L, C, wstride);
    }
}

// round 7
// speedup vs baseline: 1.0216x; 1.0216x over previous
#include <cuda_runtime.h>
#include <math.h>
#include <stdint.h>

// ---------------------------------------------------------------------------
// QuickPatternMatchingLoss
//   out[b] = log( (1/ls) * sum_{l: mask} sum_o ss_hmm[o,l] *
//                 softmax_o( W[:, :20] . x[b,1:,l] + slog[:,l] ) )
//   slog[o,l] = b[o] + sum_h W[o,20+h] * seq_hmm[h,l]   (tiny prologue kernel)
//   mask[b,l] = ( max_{c>=1} x[b,c,l] > x[b,0,l] )
//
// R7: TMA row fetch split into 3 chunks (7 channels each, 14336 B), all
// issued up front on separate mbarriers. Compute chunk k overlaps the fill
// of chunks k+1..2, collapsing the serial fill->compute structure that
// capped R6 at DRAM=65%. Same smem footprint (43 KB, 5 CTAs/SM).
// ---------------------------------------------------------------------------

#define MAX_L 2048
__device__ float g_slog[3 * MAX_L];   // batch-invariant logits

// fixed fast-path shape
#define FL 512                        // L
#define FC 21                         // channels
#define CPC 7                         // channels per TMA chunk
#define NCHUNK 3
#define CHUNK_BYTES (CPC * FL * 4)    // 14336
#define ROW_BYTES (FC * FL * 4)       // 43008

__device__ __forceinline__ uint32_t smem_u32(const void* p) {
    uint32_t a;
    asm("{ .reg .u64 t; cvta.to.shared.u64 t, %1; cvt.u32.u64 %0, t; }"
        : "=r"(a) : "l"(p));
    return a;
}
__device__ __forceinline__ void mbar_init(uint32_t mbar, uint32_t count) {
    asm volatile("mbarrier.init.shared.b64 [%0], %1;" :: "r"(mbar), "r"(count) : "memory");
}
__device__ __forceinline__ void mbar_expect_tx(uint32_t mbar, uint32_t bytes) {
    asm volatile("mbarrier.arrive.expect_tx.shared.b64 _, [%0], %1;"
                 :: "r"(mbar), "r"(bytes) : "memory");
}
__device__ __forceinline__ void bulk_g2s(uint32_t dst, const void* src,
                                         uint32_t bytes, uint32_t mbar) {
    asm volatile(
        "cp.async.bulk.shared::cta.global.mbarrier::complete_tx::bytes "
        "[%0], [%1], %2, [%3];"
        :: "r"(dst), "l"(src), "r"(bytes), "r"(mbar) : "memory");
}
__device__ __forceinline__ void mbar_wait(uint32_t mbar, uint32_t parity) {
    uint32_t done;
    asm volatile(
        "{\n\t.reg .pred p;\n\t"
        "mbarrier.try_wait.parity.acquire.cta.shared::cta.b64 p, [%1], %2;\n\t"
        "selp.b32 %0, 1, 0, p;\n\t}"
        : "=r"(done) : "r"(mbar), "r"(parity) : "memory");
    if (!done) {
        asm volatile(
            "{\n\t.reg .pred P1;\n\t"
            "WAIT_LOOP_%=:\n\t"
            "mbarrier.try_wait.parity.acquire.cta.shared::cta.b64 P1, [%0], %1, 0x989680;\n\t"
            "@P1 bra.uni WAIT_DONE_%=;\n\t"
            "bra.uni WAIT_LOOP_%=;\n\t"
            "WAIT_DONE_%=:\n\t}"
            :: "r"(mbar), "r"(parity) : "memory");
    }
}

// ---- prologue: slog[o,l] = b[o] + sum_h W[o,20+h] * seq_hmm[h,l] ----------
__global__ void slog_kernel(const float* __restrict__ seq_hmm,
                            const float* __restrict__ W,
                            const float* __restrict__ bvec,
                            int L, int H, int wstride)
{
    int l = blockIdx.x * blockDim.x + threadIdx.x;
    if (l >= L) return;
    float s0 = bvec[0], s1 = bvec[1], s2 = bvec[2];
    for (int h = 0; h < H; ++h) {
        float v = __ldg(&seq_hmm[h * L + l]);
        s0 = fmaf(__ldg(&W[0 * wstride + 20 + h]), v, s0);
        s1 = fmaf(__ldg(&W[1 * wstride + 20 + h]), v, s1);
        s2 = fmaf(__ldg(&W[2 * wstride + 20 + h]), v, s2);
    }
    g_slog[0 * L + l] = s0;
    g_slog[1 * L + l] = s1;
    g_slog[2 * L + l] = s2;
}

// ---- fast-path main kernel: 3-chunk pipelined TMA + smem compute -----------
__global__ void __launch_bounds__(128, 5)
qpml_tma(const float* __restrict__ x,
         const float* __restrict__ ss_hmm,
         const float* __restrict__ W,
         float* __restrict__ out,
         int wstride)
{
    const int b = blockIdx.x;
    const int t = threadIdx.x;

    __shared__ __align__(16) float x_s[FC * FL];   // 43008 B
    __shared__ float sW0[20], sW1[20], sW2[20];
    __shared__ __align__(8) unsigned long long mbar_storage[NCHUNK];
    __shared__ float rs[2][4];

    if (t < NCHUNK) mbar_init(smem_u32(&mbar_storage[t]), 1);
    if (t < 20) {
        sW0[t] = __ldg(&W[0 * wstride + t]);
        sW1[t] = __ldg(&W[1 * wstride + t]);
        sW2[t] = __ldg(&W[2 * wstride + t]);
    }
    __syncthreads();

    if (t == 0) {
        const char* src = (const char*)x + (size_t)b * ROW_BYTES;
        #pragma unroll
        for (int k = 0; k < NCHUNK; ++k) {
            uint32_t mb = smem_u32(&mbar_storage[k]);
            mbar_expect_tx(mb, CHUNK_BYTES);
            bulk_g2s(smem_u32(x_s) + k * CHUNK_BYTES,
                     src + k * CHUNK_BYTES, CHUNK_BYTES, mb);
        }
    }

    // L2-hot table loads in flight while TMA fills smem.
    const int i = t;                      // float4 column-group, 128 of them
    float4 sl0 = __ldg((const float4*)&g_slog[0 * FL] + i);
    float4 sl1 = __ldg((const float4*)&g_slog[1 * FL] + i);
    float4 sl2 = __ldg((const float4*)&g_slog[2 * FL] + i);
    float4 h0  = __ldg((const float4*)&ss_hmm[0 * FL] + i);
    float4 h1  = __ldg((const float4*)&ss_hmm[1 * FL] + i);
    float4 h2  = __ldg((const float4*)&ss_hmm[2 * FL] + i);

    float x0[4];
    float mx[4] = {-INFINITY, -INFINITY, -INFINITY, -INFINITY};
    float a0[4] = {0.f, 0.f, 0.f, 0.f};
    float a1[4] = {0.f, 0.f, 0.f, 0.f};
    float a2[4] = {0.f, 0.f, 0.f, 0.f};

    // ---- chunk 0: channels 0..6 (channel 0 = gap) ----
    mbar_wait(smem_u32(&mbar_storage[0]), 0);
    {
        float4 v0 = ((const float4*)x_s)[i];
        x0[0] = v0.x; x0[1] = v0.y; x0[2] = v0.z; x0[3] = v0.w;
        #pragma unroll
        for (int c = 1; c < CPC; ++c) {
            float4 v = ((const float4*)x_s)[c * (FL / 4) + i];
            float vv[4] = {v.x, v.y, v.z, v.w};
            float w0 = sW0[c - 1], w1 = sW1[c - 1], w2 = sW2[c - 1];
            #pragma unroll
            for (int j = 0; j < 4; ++j) {
                mx[j] = fmaxf(mx[j], vv[j]);
                a0[j] = fmaf(w0, vv[j], a0[j]);
                a1[j] = fmaf(w1, vv[j], a1[j]);
                a2[j] = fmaf(w2, vv[j], a2[j]);
            }
        }
    }
    // ---- chunks 1,2: channels 7..13, 14..20 ----
    #pragma unroll
    for (int k = 1; k < NCHUNK; ++k) {
        mbar_wait(smem_u32(&mbar_storage[k]), 0);
        #pragma unroll
        for (int cc = 0; cc < CPC; ++cc) {
            int c = k * CPC + cc;
            float4 v = ((const float4*)x_s)[c * (FL / 4) + i];
            float vv[4] = {v.x, v.y, v.z, v.w};
            float w0 = sW0[c - 1], w1 = sW1[c - 1], w2 = sW2[c - 1];
            #pragma unroll
            for (int j = 0; j < 4; ++j) {
                mx[j] = fmaxf(mx[j], vv[j]);
                a0[j] = fmaf(w0, vv[j], a0[j]);
                a1[j] = fmaf(w1, vv[j], a1[j]);
                a2[j] = fmaf(w2, vv[j], a2[j]);
            }
        }
    }

    float sla0[4] = {sl0.x, sl0.y, sl0.z, sl0.w};
    float sla1[4] = {sl1.x, sl1.y, sl1.z, sl1.w};
    float sla2[4] = {sl2.x, sl2.y, sl2.z, sl2.w};
    float ha0[4]  = {h0.x, h0.y, h0.z, h0.w};
    float ha1[4]  = {h1.x, h1.y, h1.z, h1.w};
    float ha2[4]  = {h2.x, h2.y, h2.z, h2.w};

    float contrib = 0.f, cnt = 0.f;
    #pragma unroll
    for (int j = 0; j < 4; ++j) {
        float e0 = __expf(a0[j] + sla0[j]);
        float e1 = __expf(a1[j] + sla1[j]);
        float e2 = __expf(a2[j] + sla2[j]);
        float num = ha0[j] * e0 + ha1[j] * e1 + ha2[j] * e2;
        float den = e0 + e1 + e2;
        bool m = mx[j] > x0[j];
        contrib += m ? __fdividef(num, den) : 0.f;
        cnt     += m ? 1.f : 0.f;
    }

    #pragma unroll
    for (int off = 16; off > 0; off >>= 1) {
        contrib += __shfl_down_sync(0xffffffffu, contrib, off);
        cnt     += __shfl_down_sync(0xffffffffu, cnt, off);
    }
    if ((t & 31) == 0) { rs[0][t >> 5] = contrib; rs[1][t >> 5] = cnt; }
    __syncthreads();
    if (t == 0) {
        float s = rs[0][0] + rs[0][1] + rs[0][2] + rs[0][3];
        float c = rs[1][0] + rs[1][1] + rs[1][2] + rs[1][3];
        out[b] = logf(s / c);
    }
}

// ---- general fallback (R5 path) ---------------------------------------------
__global__ void __launch_bounds__(128, 6)
qpml_generic(const float* __restrict__ x,
             const float* __restrict__ ss_hmm,
             const float* __restrict__ W,
             float* __restrict__ out,
             int L, int C, int wstride)
{
    const int b = blockIdx.x;
    const int t = threadIdx.x;
    const int Lv = L >> 2;

    __shared__ float sW0[20], sW1[20], sW2[20];
    if (t < 20) {
        sW0[t] = __ldg(&W[0 * wstride + t]);
        sW1[t] = __ldg(&W[1 * wstride + t]);
        sW2[t] = __ldg(&W[2 * wstride + t]);
    }
    __syncthreads();

    const float4* xb = (const float4*)(x + (size_t)b * (size_t)C * (size_t)L);
    float contrib = 0.f, cnt = 0.f;

    for (int i = t; i < Lv; i += 128) {
        float4 sl0 = __ldg((const float4*)&g_slog[0 * L] + i);
        float4 sl1 = __ldg((const float4*)&g_slog[1 * L] + i);
        float4 sl2 = __ldg((const float4*)&g_slog[2 * L] + i);
        float4 h0  = __ldg((const float4*)&ss_hmm[0 * L] + i);
        float4 h1  = __ldg((const float4*)&ss_hmm[1 * L] + i);
        float4 h2  = __ldg((const float4*)&ss_hmm[2 * L] + i);

        float4 v0 = __ldcs(&xb[i]);
        float x0[4] = {v0.x, v0.y, v0.z, v0.w};
        float mx[4] = {-INFINITY, -INFINITY, -INFINITY, -INFINITY};
        float a0[4] = {0.f, 0.f, 0.f, 0.f};
        float a1[4] = {0.f, 0.f, 0.f, 0.f};
        float a2[4] = {0.f, 0.f, 0.f, 0.f};

        for (int c = 1; c < C; ++c) {
            float4 v = __ldcs(&xb[c * Lv + i]);
            float vv[4] = {v.x, v.y, v.z, v.w};
            float w0 = sW0[c - 1], w1 = sW1[c - 1], w2 = sW2[c - 1];
            #pragma unroll
            for (int j = 0; j < 4; ++j) {
                mx[j] = fmaxf(mx[j], vv[j]);
                a0[j] = fmaf(w0, vv[j], a0[j]);
                a1[j] = fmaf(w1, vv[j], a1[j]);
                a2[j] = fmaf(w2, vv[j], a2[j]);
            }
        }

        float sla0[4] = {sl0.x, sl0.y, sl0.z, sl0.w};
        float sla1[4] = {sl1.x, sl1.y, sl1.z, sl1.w};
        float sla2[4] = {sl2.x, sl2.y, sl2.z, sl2.w};
        float ha0[4]  = {h0.x, h0.y, h0.z, h0.w};
        float ha1[4]  = {h1.x, h1.y, h1.z, h1.w};
        float ha2[4]  = {h2.x, h2.y, h2.z, h2.w};

        #pragma unroll
        for (int j = 0; j < 4; ++j) {
            float e0 = __expf(a0[j] + sla0[j]);
            float e1 = __expf(a1[j] + sla1[j]);
            float e2 = __expf(a2[j] + sla2[j]);
            float num = ha0[j] * e0 + ha1[j] * e1 + ha2[j] * e2;
            float den = e0 + e1 + e2;
            bool m = mx[j] > x0[j];
            contrib += m ? __fdividef(num, den) : 0.f;
            cnt     += m ? 1.f : 0.f;
        }
    }

    #pragma unroll
    for (int off = 16; off > 0; off >>= 1) {
        contrib += __shfl_down_sync(0xffffffffu, contrib, off);
        cnt     += __shfl_down_sync(0xffffffffu, cnt, off);
    }
    __shared__ float rs[2][4];
    if ((t & 31) == 0) { rs[0][t >> 5] = contrib; rs[1][t >> 5] = cnt; }
    __syncthreads();
    if (t == 0) {
        float s = rs[0][0] + rs[0][1] + rs[0][2] + rs[0][3];
        float c = rs[1][0] + rs[1][1] + rs[1][2] + rs[1][3];
        out[b] = logf(s / c);
    }
}

__global__ void qpml_kernel_scalar(const float* __restrict__ x,
                                   const float* __restrict__ ss_hmm,
                                   const float* __restrict__ W,
                                   float* __restrict__ out,
                                   int L, int C, int wstride)
{
    const int b = blockIdx.x;
    const int t = threadIdx.x;
    const float* xb = x + (size_t)b * (size_t)C * (size_t)L;

    float contrib = 0.f, cnt = 0.f;
    for (int l = t; l < L; l += blockDim.x) {
        float x0 = xb[l];
        float mx = -INFINITY;
        float a0 = 0.f, a1 = 0.f, a2 = 0.f;
        for (int c = 1; c < C; ++c) {
            float v = xb[c * L + l];
            mx = fmaxf(mx, v);
            a0 = fmaf(W[0 * wstride + c - 1], v, a0);
            a1 = fmaf(W[1 * wstride + c - 1], v, a1);
            a2 = fmaf(W[2 * wstride + c - 1], v, a2);
        }
        float e0 = __expf(a0 + g_slog[0 * L + l]);
        float e1 = __expf(a1 + g_slog[1 * L + l]);
        float e2 = __expf(a2 + g_slog[2 * L + l]);
        float num = ss_hmm[0 * L + l] * e0 + ss_hmm[1 * L + l] * e1
                  + ss_hmm[2 * L + l] * e2;
        if (mx > x0) { contrib += num / (e0 + e1 + e2); cnt += 1.f; }
    }
    #pragma unroll
    for (int off = 16; off > 0; off >>= 1) {
        contrib += __shfl_down_sync(0xffffffffu, contrib, off);
        cnt     += __shfl_down_sync(0xffffffffu, cnt, off);
    }
    __shared__ float rs[2][32];
    int nw = (blockDim.x + 31) >> 5;
    if ((t & 31) == 0) { rs[0][t >> 5] = contrib; rs[1][t >> 5] = cnt; }
    __syncthreads();
    if (t == 0) {
        float s = 0.f, c = 0.f;
        for (int w = 0; w < nw; ++w) { s += rs[0][w]; c += rs[1][w]; }
        out[b] = logf(s / c);
    }
}

extern "C" void kernel_launch(void* const* d_in, const int* in_sizes, int n_in,
                              void* d_out, int out_size)
{
    const float* x       = (const float*)d_in[0];   // [B, 21, L]
    const float* seq_hmm = (const float*)d_in[1];   // [H, L]
    const float* ss_hmm  = (const float*)d_in[2];   // [3, L]
    const float* W       = (const float*)d_in[3];   // [3, 20+H]
    const float* bvec    = (const float*)d_in[4];   // [3]
    float* out = (float*)d_out;

    const int B       = out_size;                   // 4096
    const int L       = in_sizes[2] / 3;            // 512
    const int H       = in_sizes[1] / L;            // 30
    const int C       = in_sizes[0] / (B * L);      // 21
    const int wstride = in_sizes[3] / 3;            // 20 + H = 50

    slog_kernel<<<(L + 255) / 256, 256>>>(seq_hmm, W, bvec, L, H, wstride);

    if (C == FC && L == FL) {
        qpml_tma<<<B, 128>>>(x, ss_hmm, W, out, wstride);
    } else if ((L & 3) == 0 && L <= MAX_L) {
        qpml_generic<<<B, 128>>>(x, ss_hmm, W, out, L, C, wstride);
    } else {
        qpml_kernel_scalar<<<B, 128>>>(x, ss_hmm, W, out, L, C, wstride);
    }
}

// round 8
// speedup vs baseline: 1.1993x; 1.1739x over previous
#include <cuda_runtime.h>
#include <math.h>
#include <stdint.h>

// ---------------------------------------------------------------------------
// QuickPatternMatchingLoss
//   out[b] = log( (1/ls) * sum_{l: mask} sum_o ss_hmm[o,l] *
//                 softmax_o( W[:, :20] . x[b,1:,l] + slog[:,l] ) )
//   slog[o,l] = b[o] + sum_h W[o,20+h] * seq_hmm[h,l]
//   mask[b,l] = ( max_{c>=1} x[b,c,l] > x[b,0,l] )
//
// R8: persistent double-buffered TMA. 304 CTAs (2/SM, one wave), each owns
// ~14 rows. Two 43 KB smem buffers: while computing row n from buffer k,
// buffer k^1 fills row n+1 via cp.async.bulk. slog + ss_hmm live in 24
// registers per thread (thread t always handles column group t), computed
// once per CTA under the first fill -> no prologue kernel, single launch.
// R7 lesson: do NOT chunk within a row. R6 lesson: TMA removes the register
// front-batching limit; R2/R4 persistent-loop failures don't apply to TMA.
// ---------------------------------------------------------------------------

#define MAX_L 2048
__device__ float g_slog[3 * MAX_L];   // fallback path scratch

#define FL 512
#define FC 21
#define FL4 (FL / 4)                   // 128 float4 per channel row
#define ROW_BYTES (FC * FL * 4)        // 43008
#define GRIDP 304                      // 2 CTAs/SM x 152 SMs
#define SMEM_DYN (2 * ROW_BYTES)       // 86016

__device__ __forceinline__ uint32_t smem_u32(const void* p) {
    uint32_t a;
    asm("{ .reg .u64 t; cvta.to.shared.u64 t, %1; cvt.u32.u64 %0, t; }"
        : "=r"(a) : "l"(p));
    return a;
}
__device__ __forceinline__ void mbar_init(uint32_t mbar, uint32_t count) {
    asm volatile("mbarrier.init.shared.b64 [%0], %1;" :: "r"(mbar), "r"(count) : "memory");
}
__device__ __forceinline__ void mbar_expect_tx(uint32_t mbar, uint32_t bytes) {
    asm volatile("mbarrier.arrive.expect_tx.shared.b64 _, [%0], %1;"
                 :: "r"(mbar), "r"(bytes) : "memory");
}
__device__ __forceinline__ void bulk_g2s(uint32_t dst, const void* src,
                                         uint32_t bytes, uint32_t mbar) {
    asm volatile(
        "cp.async.bulk.shared::cta.global.mbarrier::complete_tx::bytes "
        "[%0], [%1], %2, [%3];"
        :: "r"(dst), "l"(src), "r"(bytes), "r"(mbar) : "memory");
}
__device__ __forceinline__ void mbar_wait(uint32_t mbar, uint32_t parity) {
    uint32_t done;
    asm volatile(
        "{\n\t.reg .pred p;\n\t"
        "mbarrier.try_wait.parity.acquire.cta.shared::cta.b64 p, [%1], %2;\n\t"
        "selp.b32 %0, 1, 0, p;\n\t}"
        : "=r"(done) : "r"(mbar), "r"(parity) : "memory");
    if (!done) {
        asm volatile(
            "{\n\t.reg .pred P1;\n\t"
            "WAIT_LOOP_%=:\n\t"
            "mbarrier.try_wait.parity.acquire.cta.shared::cta.b64 P1, [%0], %1, 0x989680;\n\t"
            "@P1 bra.uni WAIT_DONE_%=;\n\t"
            "bra.uni WAIT_LOOP_%=;\n\t"
            "WAIT_DONE_%=:\n\t}"
            :: "r"(mbar), "r"(parity) : "memory");
    }
}

struct Tables {
    float4 sl0, sl1, sl2, h0, h1, h2;
};

__device__ __forceinline__ void process_row(
    const float4* __restrict__ buf, uint32_t buf_sm, uint32_t mbar, int phase,
    const float* __restrict__ sW0, const float* __restrict__ sW1,
    const float* __restrict__ sW2,
    const Tables& tb, int t,
    volatile float* rs0, volatile float* rs1,
    float* __restrict__ out, int r,
    const float* __restrict__ x, int refill_row)
{
    mbar_wait(mbar, phase);

    float4 v0 = buf[t];                       // gap channel
    float x0[4] = {v0.x, v0.y, v0.z, v0.w};
    float mx[4] = {-INFINITY, -INFINITY, -INFINITY, -INFINITY};
    float a0[4] = {0.f, 0.f, 0.f, 0.f};
    float a1[4] = {0.f, 0.f, 0.f, 0.f};
    float a2[4] = {0.f, 0.f, 0.f, 0.f};

    #pragma unroll
    for (int c = 1; c < FC; ++c) {
        float4 v = buf[c * FL4 + t];
        float vv[4] = {v.x, v.y, v.z, v.w};
        float w0 = sW0[c - 1], w1 = sW1[c - 1], w2 = sW2[c - 1];
        #pragma unroll
        for (int j = 0; j < 4; ++j) {
            mx[j] = fmaxf(mx[j], vv[j]);
            a0[j] = fmaf(w0, vv[j], a0[j]);
            a1[j] = fmaf(w1, vv[j], a1[j]);
            a2[j] = fmaf(w2, vv[j], a2[j]);
        }
    }

    float sla0[4] = {tb.sl0.x, tb.sl0.y, tb.sl0.z, tb.sl0.w};
    float sla1[4] = {tb.sl1.x, tb.sl1.y, tb.sl1.z, tb.sl1.w};
    float sla2[4] = {tb.sl2.x, tb.sl2.y, tb.sl2.z, tb.sl2.w};
    float ha0[4]  = {tb.h0.x, tb.h0.y, tb.h0.z, tb.h0.w};
    float ha1[4]  = {tb.h1.x, tb.h1.y, tb.h1.z, tb.h1.w};
    float ha2[4]  = {tb.h2.x, tb.h2.y, tb.h2.z, tb.h2.w};

    float contrib = 0.f, cnt = 0.f;
    #pragma unroll
    for (int j = 0; j < 4; ++j) {
        float e0 = __expf(a0[j] + sla0[j]);
        float e1 = __expf(a1[j] + sla1[j]);
        float e2 = __expf(a2[j] + sla2[j]);
        float num = ha0[j] * e0 + ha1[j] * e1 + ha2[j] * e2;
        float den = e0 + e1 + e2;
        bool m = mx[j] > x0[j];
        contrib += m ? __fdividef(num, den) : 0.f;
        cnt     += m ? 1.f : 0.f;
    }

    #pragma unroll
    for (int off = 16; off > 0; off >>= 1) {
        contrib += __shfl_down_sync(0xffffffffu, contrib, off);
        cnt     += __shfl_down_sync(0xffffffffu, cnt, off);
    }
    if ((t & 31) == 0) { rs0[t >> 5] = contrib; rs1[t >> 5] = cnt; }
    __syncthreads();          // all threads done reading buf + rs visible
    if (t == 0) {
        float s = rs0[0] + rs0[1] + rs0[2] + rs0[3];
        float c = rs1[0] + rs1[1] + rs1[2] + rs1[3];
        out[r] = logf(s / c);
        if (refill_row >= 0) {
            mbar_expect_tx(mbar, ROW_BYTES);
            bulk_g2s(buf_sm, (const char*)x + (size_t)refill_row * ROW_BYTES,
                     ROW_BYTES, mbar);
        }
    }
    __syncthreads();          // protect rs reuse on next row
}

// ---- persistent double-buffered fast path -----------------------------------
__global__ void __launch_bounds__(128, 2)
qpml_persist(const float* __restrict__ x,
             const float* __restrict__ seq_hmm,
             const float* __restrict__ ss_hmm,
             const float* __restrict__ W,
             const float* __restrict__ bvec,
             float* __restrict__ out,
             int B, int H, int wstride)
{
    extern __shared__ __align__(16) float4 dyn[];
    float4* buf0 = dyn;
    float4* buf1 = dyn + FC * FL4;

    __shared__ float sW0[64], sW1[64], sW2[64];
    __shared__ __align__(8) unsigned long long mb[2];
    __shared__ float rs0[4], rs1[4];

    const int t = threadIdx.x;
    const int cta = blockIdx.x;
    const int G = gridDim.x;

    if (t < 2) mbar_init(smem_u32(&mb[t]), 1);
    if (t < wstride && t < 64) {
        sW0[t] = __ldg(&W[0 * wstride + t]);
        sW1[t] = __ldg(&W[1 * wstride + t]);
        sW2[t] = __ldg(&W[2 * wstride + t]);
    }
    __syncthreads();

    const uint32_t buf0_sm = smem_u32(buf0);
    const uint32_t buf1_sm = smem_u32(buf1);
    const uint32_t mb0 = smem_u32(&mb[0]);
    const uint32_t mb1 = smem_u32(&mb[1]);

    // prefill both buffers
    if (t == 0) {
        if (cta < B) {
            mbar_expect_tx(mb0, ROW_BYTES);
            bulk_g2s(buf0_sm, (const char*)x + (size_t)cta * ROW_BYTES,
                     ROW_BYTES, mb0);
        }
        if (cta + G < B) {
            mbar_expect_tx(mb1, ROW_BYTES);
            bulk_g2s(buf1_sm, (const char*)x + (size_t)(cta + G) * ROW_BYTES,
                     ROW_BYTES, mb1);
        }
    }

    // per-thread tables (computed under the first fill):
    // slog[o, 4t..4t+3] and ss_hmm[o, 4t..4t+3] in 24 registers
    Tables tb;
    {
        float bb0 = __ldg(&bvec[0]), bb1 = __ldg(&bvec[1]), bb2 = __ldg(&bvec[2]);
        tb.sl0 = make_float4(bb0, bb0, bb0, bb0);
        tb.sl1 = make_float4(bb1, bb1, bb1, bb1);
        tb.sl2 = make_float4(bb2, bb2, bb2, bb2);
        for (int h = 0; h < H; ++h) {
            float4 v = __ldg((const float4*)seq_hmm + h * FL4 + t);
            float w0 = sW0[20 + h], w1 = sW1[20 + h], w2 = sW2[20 + h];
            tb.sl0.x = fmaf(w0, v.x, tb.sl0.x); tb.sl0.y = fmaf(w0, v.y, tb.sl0.y);
            tb.sl0.z = fmaf(w0, v.z, tb.sl0.z); tb.sl0.w = fmaf(w0, v.w, tb.sl0.w);
            tb.sl1.x = fmaf(w1, v.x, tb.sl1.x); tb.sl1.y = fmaf(w1, v.y, tb.sl1.y);
            tb.sl1.z = fmaf(w1, v.z, tb.sl1.z); tb.sl1.w = fmaf(w1, v.w, tb.sl1.w);
            tb.sl2.x = fmaf(w2, v.x, tb.sl2.x); tb.sl2.y = fmaf(w2, v.y, tb.sl2.y);
            tb.sl2.z = fmaf(w2, v.z, tb.sl2.z); tb.sl2.w = fmaf(w2, v.w, tb.sl2.w);
        }
        tb.h0 = __ldg((const float4*)ss_hmm + 0 * FL4 + t);
        tb.h1 = __ldg((const float4*)ss_hmm + 1 * FL4 + t);
        tb.h2 = __ldg((const float4*)ss_hmm + 2 * FL4 + t);
    }

    int ph0 = 0, ph1 = 0;
    for (int r = cta; r < B; ) {
        {
            int rf = (r + 2 * G < B) ? r + 2 * G : -1;
            process_row(buf0, buf0_sm, mb0, ph0, sW0, sW1, sW2, tb, t,
                        rs0, rs1, out, r, x, rf);
            ph0 ^= 1;
        }
        r += G;
        if (r >= B) break;
        {
            int rf = (r + 2 * G < B) ? r + 2 * G : -1;
            process_row(buf1, buf1_sm, mb1, ph1, sW0, sW1, sW2, tb, t,
                        rs0, rs1, out, r, x, rf);
            ph1 ^= 1;
        }
        r += G;
    }
}

// ---- fallback paths (non-512x21 shapes) --------------------------------------
__global__ void slog_kernel(const float* __restrict__ seq_hmm,
                            const float* __restrict__ W,
                            const float* __restrict__ bvec,
                            int L, int H, int wstride)
{
    int l = blockIdx.x * blockDim.x + threadIdx.x;
    if (l >= L) return;
    float s0 = bvec[0], s1 = bvec[1], s2 = bvec[2];
    for (int h = 0; h < H; ++h) {
        float v = __ldg(&seq_hmm[h * L + l]);
        s0 = fmaf(__ldg(&W[0 * wstride + 20 + h]), v, s0);
        s1 = fmaf(__ldg(&W[1 * wstride + 20 + h]), v, s1);
        s2 = fmaf(__ldg(&W[2 * wstride + 20 + h]), v, s2);
    }
    g_slog[0 * L + l] = s0;
    g_slog[1 * L + l] = s1;
    g_slog[2 * L + l] = s2;
}

__global__ void __launch_bounds__(128, 6)
qpml_generic(const float* __restrict__ x,
             const float* __restrict__ ss_hmm,
             const float* __restrict__ W,
             float* __restrict__ out,
             int L, int C, int wstride)
{
    const int b = blockIdx.x;
    const int t = threadIdx.x;
    const int Lv = L >> 2;

    __shared__ float sW0[20], sW1[20], sW2[20];
    if (t < 20) {
        sW0[t] = __ldg(&W[0 * wstride + t]);
        sW1[t] = __ldg(&W[1 * wstride + t]);
        sW2[t] = __ldg(&W[2 * wstride + t]);
    }
    __syncthreads();

    const float4* xb = (const float4*)(x + (size_t)b * (size_t)C * (size_t)L);
    float contrib = 0.f, cnt = 0.f;

    for (int i = t; i < Lv; i += 128) {
        float4 sl0 = __ldg((const float4*)&g_slog[0 * L] + i);
        float4 sl1 = __ldg((const float4*)&g_slog[1 * L] + i);
        float4 sl2 = __ldg((const float4*)&g_slog[2 * L] + i);
        float4 h0  = __ldg((const float4*)&ss_hmm[0 * L] + i);
        float4 h1  = __ldg((const float4*)&ss_hmm[1 * L] + i);
        float4 h2  = __ldg((const float4*)&ss_hmm[2 * L] + i);

        float4 v0 = __ldcs(&xb[i]);
        float x0[4] = {v0.x, v0.y, v0.z, v0.w};
        float mx[4] = {-INFINITY, -INFINITY, -INFINITY, -INFINITY};
        float a0[4] = {0.f, 0.f, 0.f, 0.f};
        float a1[4] = {0.f, 0.f, 0.f, 0.f};
        float a2[4] = {0.f, 0.f, 0.f, 0.f};

        for (int c = 1; c < C; ++c) {
            float4 v = __ldcs(&xb[c * Lv + i]);
            float vv[4] = {v.x, v.y, v.z, v.w};
            float w0 = sW0[c - 1], w1 = sW1[c - 1], w2 = sW2[c - 1];
            #pragma unroll
            for (int j = 0; j < 4; ++j) {
                mx[j] = fmaxf(mx[j], vv[j]);
                a0[j] = fmaf(w0, vv[j], a0[j]);
                a1[j] = fmaf(w1, vv[j], a1[j]);
                a2[j] = fmaf(w2, vv[j], a2[j]);
            }
        }

        float sla0[4] = {sl0.x, sl0.y, sl0.z, sl0.w};
        float sla1[4] = {sl1.x, sl1.y, sl1.z, sl1.w};
        float sla2[4] = {sl2.x, sl2.y, sl2.z, sl2.w};
        float ha0[4]  = {h0.x, h0.y, h0.z, h0.w};
        float ha1[4]  = {h1.x, h1.y, h1.z, h1.w};
        float ha2[4]  = {h2.x, h2.y, h2.z, h2.w};

        #pragma unroll
        for (int j = 0; j < 4; ++j) {
            float e0 = __expf(a0[j] + sla0[j]);
            float e1 = __expf(a1[j] + sla1[j]);
            float e2 = __expf(a2[j] + sla2[j]);
            float num = ha0[j] * e0 + ha1[j] * e1 + ha2[j] * e2;
            float den = e0 + e1 + e2;
            bool m = mx[j] > x0[j];
            contrib += m ? __fdividef(num, den) : 0.f;
            cnt     += m ? 1.f : 0.f;
        }
    }

    #pragma unroll
    for (int off = 16; off > 0; off >>= 1) {
        contrib += __shfl_down_sync(0xffffffffu, contrib, off);
        cnt     += __shfl_down_sync(0xffffffffu, cnt, off);
    }
    __shared__ float rs[2][4];
    if ((t & 31) == 0) { rs[0][t >> 5] = contrib; rs[1][t >> 5] = cnt; }
    __syncthreads();
    if (t == 0) {
        float s = rs[0][0] + rs[0][1] + rs[0][2] + rs[0][3];
        float c = rs[1][0] + rs[1][1] + rs[1][2] + rs[1][3];
        out[b] = logf(s / c);
    }
}

__global__ void qpml_kernel_scalar(const float* __restrict__ x,
                                   const float* __restrict__ ss_hmm,
                                   const float* __restrict__ W,
                                   float* __restrict__ out,
                                   int L, int C, int wstride)
{
    const int b = blockIdx.x;
    const int t = threadIdx.x;
    const float* xb = x + (size_t)b * (size_t)C * (size_t)L;

    float contrib = 0.f, cnt = 0.f;
    for (int l = t; l < L; l += blockDim.x) {
        float x0 = xb[l];
        float mx = -INFINITY;
        float a0 = 0.f, a1 = 0.f, a2 = 0.f;
        for (int c = 1; c < C; ++c) {
            float v = xb[c * L + l];
            mx = fmaxf(mx, v);
            a0 = fmaf(W[0 * wstride + c - 1], v, a0);
            a1 = fmaf(W[1 * wstride + c - 1], v, a1);
            a2 = fmaf(W[2 * wstride + c - 1], v, a2);
        }
        float e0 = __expf(a0 + g_slog[0 * L + l]);
        float e1 = __expf(a1 + g_slog[1 * L + l]);
        float e2 = __expf(a2 + g_slog[2 * L + l]);
        float num = ss_hmm[0 * L + l] * e0 + ss_hmm[1 * L + l] * e1
                  + ss_hmm[2 * L + l] * e2;
        if (mx > x0) { contrib += num / (e0 + e1 + e2); cnt += 1.f; }
    }
    #pragma unroll
    for (int off = 16; off > 0; off >>= 1) {
        contrib += __shfl_down_sync(0xffffffffu, contrib, off);
        cnt     += __shfl_down_sync(0xffffffffu, cnt, off);
    }
    __shared__ float rs[2][32];
    int nw = (blockDim.x + 31) >> 5;
    if ((t & 31) == 0) { rs[0][t >> 5] = contrib; rs[1][t >> 5] = cnt; }
    __syncthreads();
    if (t == 0) {
        float s = 0.f, c = 0.f;
        for (int w = 0; w < nw; ++w) { s += rs[0][w]; c += rs[1][w]; }
        out[b] = logf(s / c);
    }
}

extern "C" void kernel_launch(void* const* d_in, const int* in_sizes, int n_in,
                              void* d_out, int out_size)
{
    const float* x       = (const float*)d_in[0];   // [B, 21, L]
    const float* seq_hmm = (const float*)d_in[1];   // [H, L]
    const float* ss_hmm  = (const float*)d_in[2];   // [3, L]
    const float* W       = (const float*)d_in[3];   // [3, 20+H]
    const float* bvec    = (const float*)d_in[4];   // [3]
    float* out = (float*)d_out;

    const int B       = out_size;                   // 4096
    const int L       = in_sizes[2] / 3;            // 512
    const int H       = in_sizes[1] / L;            // 30
    const int C       = in_sizes[0] / (B * L);      // 21
    const int wstride = in_sizes[3] / 3;            // 20 + H = 50

    if (C == FC && L == FL && H <= 44 && wstride <= 64) {
        cudaFuncSetAttribute(qpml_persist,
                             cudaFuncAttributeMaxDynamicSharedMemorySize,
                             SMEM_DYN);
        int grid = (B < GRIDP) ? B : GRIDP;
        qpml_persist<<<grid, 128, SMEM_DYN>>>(x, seq_hmm, ss_hmm, W, bvec,
                                              out, B, H, wstride);
    } else if ((L & 3) == 0 && L <= MAX_L) {
        slog_kernel<<<(L + 255) / 256, 256>>>(seq_hmm, W, bvec, L, H, wstride);
        qpml_generic<<<B, 128>>>(x, ss_hmm, W, out, L, C, wstride);
    } else {
        slog_kernel<<<(L + 255) / 256, 256>>>(seq_hmm, W, bvec, L, H, wstride);
        qpml_kernel_scalar<<<B, 128>>>(x, ss_hmm, W, out, L, C, wstride);
    }
}